// round 2
// baseline (speedup 1.0000x reference)
#include <cuda_runtime.h>
#include <math.h>

#define B_ 8
#define T_ 128
#define S_ 256
#define H_ 512

// Scratch (allocation-free rule: device globals)
__device__ float g_qs[B_ * T_ * H_];    // 2 MB
__device__ float g_hs[B_ * S_ * H_];    // 4 MB
__device__ float g_ctx[B_ * T_ * H_];   // 2 MB

// ---------------------------------------------------------------------------
// SGEMM "NT": C[m,n] = sum_k a(m,k) * Bw[n*K + k]
// OUTMODE: A is virtual concat [A | A2] (each row H_ wide), epilogue tanh(x+bias)
// Tiles: 64x64x16, 256 threads, 4x4 per thread.
// ---------------------------------------------------------------------------
template <bool OUTMODE>
__global__ void __launch_bounds__(256) sgemm_nt(
    const float* __restrict__ A, const float* __restrict__ A2,
    const float* __restrict__ Bw, const float* __restrict__ bias,
    float* __restrict__ C, int M, int N, int K)
{
    __shared__ float As[16][64];
    __shared__ float Bs[16][64];

    const int tid = threadIdx.x;
    const int m0 = blockIdx.y * 64;
    const int n0 = blockIdx.x * 64;
    const int tx = tid & 15;   // n
    const int ty = tid >> 4;   // m
    const int lr = tid >> 2;   // 0..63 tile row for loads
    const int lc = (tid & 3) << 2;  // 0,4,8,12 k offset

    float acc[4][4] = {};

    for (int k0 = 0; k0 < K; k0 += 16) {
        const int kk = k0 + lc;
        float4 av;
        if (OUTMODE) {
            // virtual concat: k<H_ -> A (context), else A2 (query); rows are H_ wide
            const float* src = (kk < H_) ? A : A2;
            const int kl = (kk < H_) ? kk : (kk - H_);
            av = *reinterpret_cast<const float4*>(src + (size_t)(m0 + lr) * H_ + kl);
        } else {
            av = *reinterpret_cast<const float4*>(A + (size_t)(m0 + lr) * K + kk);
        }
        const float4 bv = *reinterpret_cast<const float4*>(Bw + (size_t)(n0 + lr) * K + kk);

        As[lc + 0][lr] = av.x; As[lc + 1][lr] = av.y;
        As[lc + 2][lr] = av.z; As[lc + 3][lr] = av.w;
        Bs[lc + 0][lr] = bv.x; Bs[lc + 1][lr] = bv.y;
        Bs[lc + 2][lr] = bv.z; Bs[lc + 3][lr] = bv.w;
        __syncthreads();

        #pragma unroll
        for (int kq = 0; kq < 16; kq++) {
            const float4 a4 = *reinterpret_cast<const float4*>(&As[kq][ty << 2]);
            const float4 b4 = *reinterpret_cast<const float4*>(&Bs[kq][tx << 2]);
            const float aa[4] = {a4.x, a4.y, a4.z, a4.w};
            const float bb[4] = {b4.x, b4.y, b4.z, b4.w};
            #pragma unroll
            for (int i = 0; i < 4; i++)
                #pragma unroll
                for (int j = 0; j < 4; j++)
                    acc[i][j] = fmaf(aa[i], bb[j], acc[i][j]);
        }
        __syncthreads();
    }

    #pragma unroll
    for (int i = 0; i < 4; i++) {
        const int m = m0 + (ty << 2) + i;
        #pragma unroll
        for (int j = 0; j < 4; j++) {
            const int n = n0 + (tx << 2) + j;
            float o = acc[i][j];
            if (OUTMODE) o = tanhf(o + bias[n]);
            C[(size_t)m * N + n] = o;
        }
    }
}

// ---------------------------------------------------------------------------
// Fused attention: scores = v . tanh(qs[t] + hs[s]), masked softmax over S,
// context = attn @ enc.  Block = (b, 4 consecutive t).  256 threads = 8 warps.
// Warp w: t_loc = w>>1, handles half the s range of each 16-row hs chunk.
// q-row and v live in registers (h = lane + 32*j), hs streamed via smem.
// tanh via ex2+rcp (accurate to ~1e-6): tanh(x) = 1 - 2/(exp2(2*log2e*x)+1)
// ---------------------------------------------------------------------------
#define TT 4    // t rows per block
#define SC 16   // s rows per smem chunk

__global__ void __launch_bounds__(256) attn_kernel(
    const float* __restrict__ qs, const float* __restrict__ hs,
    const float* __restrict__ enc, const float* __restrict__ v,
    const int* __restrict__ lens, float* __restrict__ ctx)
{
    __shared__ float sh_hs[SC * H_];          // 32 KB (reused for pass-2 combine)
    __shared__ float sh_sc[TT][S_];           // 4 KB
    __shared__ float sh_rsum[TT];

    const int b    = blockIdx.y;
    const int t0   = blockIdx.x * TT;
    const int tid  = threadIdx.x;
    const int lane = tid & 31;
    const int wid  = tid >> 5;
    const int t_loc = wid >> 1;
    const int shalf = wid & 1;

    const float C2LOG2E = 2.8853900817779268f;  // 2*log2(e)

    // Preload q row + v into registers (h = lane + 32*j)
    float qreg[16], vreg[16];
    {
        const float* qrow = qs + (size_t)(b * T_ + t0 + t_loc) * H_;
        #pragma unroll
        for (int j = 0; j < 16; j++) {
            qreg[j] = qrow[lane + 32 * j];
            vreg[j] = v[lane + 32 * j];
        }
    }

    const float* hsb  = hs  + (size_t)b * S_ * H_;
    const float* encb = enc + (size_t)b * S_ * H_;

    // ---- Pass 1: scores ----
    for (int s0 = 0; s0 < S_; s0 += SC) {
        // cooperative chunk load: SC*H_ = 8192 floats, 8 float4 per thread
        #pragma unroll
        for (int r = 0; r < (SC * H_) / (256 * 4); r++) {
            const int off = (r * 256 + tid) * 4;
            *reinterpret_cast<float4*>(&sh_hs[off]) =
                *reinterpret_cast<const float4*>(&hsb[(size_t)s0 * H_ + off]);
        }
        __syncthreads();

        #pragma unroll
        for (int i = 0; i < SC / 2; i++) {
            const int sl = shalf * (SC / 2) + i;
            const float* hrow = &sh_hs[sl * H_];
            float acc = 0.f;
            #pragma unroll
            for (int j = 0; j < 16; j++) {
                const float x = qreg[j] + hrow[lane + 32 * j];
                float e;
                asm("ex2.approx.f32 %0, %1;" : "=f"(e) : "f"(x * C2LOG2E));
                float rr;
                asm("rcp.approx.f32 %0, %1;" : "=f"(rr) : "f"(e + 1.0f));
                const float th = fmaf(-2.0f, rr, 1.0f);   // tanh(x)
                acc = fmaf(th, vreg[j], acc);
            }
            acc += __shfl_xor_sync(0xffffffffu, acc, 16);
            acc += __shfl_xor_sync(0xffffffffu, acc, 8);
            acc += __shfl_xor_sync(0xffffffffu, acc, 4);
            acc += __shfl_xor_sync(0xffffffffu, acc, 2);
            acc += __shfl_xor_sync(0xffffffffu, acc, 1);
            if (lane == 0) sh_sc[t_loc][s0 + sl] = acc;
        }
        __syncthreads();
    }

    // ---- Softmax (warp per t row) ----
    const int len = lens[b];
    if (wid < TT) {
        const int t = wid;
        float vals[S_ / 32];
        float m = -1e30f;
        #pragma unroll
        for (int i = 0; i < S_ / 32; i++) {
            const int s = lane + 32 * i;
            const float sc = (s < len) ? sh_sc[t][s] : -1e30f;
            vals[i] = sc;
            m = fmaxf(m, sc);
        }
        #pragma unroll
        for (int o = 16; o; o >>= 1) m = fmaxf(m, __shfl_xor_sync(0xffffffffu, m, o));
        float sum = 0.f;
        #pragma unroll
        for (int i = 0; i < S_ / 32; i++) {
            const int s = lane + 32 * i;
            const float e = (s < len) ? __expf(vals[i] - m) : 0.f;
            sh_sc[t][s] = e;
            sum += e;
        }
        #pragma unroll
        for (int o = 16; o; o >>= 1) sum += __shfl_xor_sync(0xffffffffu, sum, o);
        if (lane == 0) sh_rsum[t] = 1.0f / sum;
    }
    __syncthreads();

    // ---- Pass 2: context = attn @ enc ----
    // group g handles s in [g*128, g*128+128); thread owns float4 column c4
    const int g  = tid >> 7;
    const int c4 = tid & 127;
    float4 acc4[TT];
    #pragma unroll
    for (int t = 0; t < TT; t++) acc4[t] = make_float4(0.f, 0.f, 0.f, 0.f);

    const int sbeg = g * (S_ / 2);
    #pragma unroll 4
    for (int s = sbeg; s < sbeg + S_ / 2; s++) {
        const float4 e4 = *reinterpret_cast<const float4*>(&encb[(size_t)s * H_ + c4 * 4]);
        #pragma unroll
        for (int t = 0; t < TT; t++) {
            const float w = sh_sc[t][s];
            acc4[t].x = fmaf(w, e4.x, acc4[t].x);
            acc4[t].y = fmaf(w, e4.y, acc4[t].y);
            acc4[t].z = fmaf(w, e4.z, acc4[t].z);
            acc4[t].w = fmaf(w, e4.w, acc4[t].w);
        }
    }

    // combine partials from the two s-halves via smem (reuse sh_hs)
    if (g == 0) {
        #pragma unroll
        for (int t = 0; t < TT; t++)
            *reinterpret_cast<float4*>(&sh_hs[(t * 128 + c4) * 4]) = acc4[t];
    }
    __syncthreads();
    if (g == 1) {
        #pragma unroll
        for (int t = 0; t < TT; t++) {
            float4 o = *reinterpret_cast<const float4*>(&sh_hs[(t * 128 + c4) * 4]);
            const float rs = sh_rsum[t];
            o.x = (o.x + acc4[t].x) * rs;
            o.y = (o.y + acc4[t].y) * rs;
            o.z = (o.z + acc4[t].z) * rs;
            o.w = (o.w + acc4[t].w) * rs;
            *reinterpret_cast<float4*>(&ctx[(size_t)(b * T_ + t0 + t) * H_ + c4 * 4]) = o;
        }
    }
}

// ---------------------------------------------------------------------------
extern "C" void kernel_launch(void* const* d_in, const int* in_sizes, int n_in,
                              void* d_out, int out_size)
{
    const float* query = (const float*)d_in[0];  // (B,T,H)
    const float* enc   = (const float*)d_in[1];  // (B,S,H)
    const int*   lens  = (const int*)d_in[2];    // (B,)
    const float* W_s   = (const float*)d_in[3];  // (H,H)
    const float* W_h   = (const float*)d_in[4];  // (H,H)
    const float* v     = (const float*)d_in[5];  // (H,)
    const float* W_out = (const float*)d_in[6];  // (H,2H)
    const float* b_out = (const float*)d_in[7];  // (H,)
    float* out = (float*)d_out;                  // (B,T,H)

    float *qs = nullptr, *hsp = nullptr, *ctx = nullptr;
    cudaGetSymbolAddress((void**)&qs,  g_qs);
    cudaGetSymbolAddress((void**)&hsp, g_hs);
    cudaGetSymbolAddress((void**)&ctx, g_ctx);

    // qs = query @ W_s^T   (M=1024, N=512, K=512)
    sgemm_nt<false><<<dim3(H_ / 64, (B_ * T_) / 64), 256>>>(
        query, nullptr, W_s, nullptr, qs, B_ * T_, H_, H_);
    // hs = enc @ W_h^T     (M=2048, N=512, K=512)
    sgemm_nt<false><<<dim3(H_ / 64, (B_ * S_) / 64), 256>>>(
        enc, nullptr, W_h, nullptr, hsp, B_ * S_, H_, H_);
    // fused scores/softmax/context
    attn_kernel<<<dim3(T_ / TT, B_), 256>>>(qs, hsp, enc, v, lens, ctx);
    // out = tanh([ctx, query] @ W_out^T + b)  (M=1024, N=512, K=1024)
    sgemm_nt<true><<<dim3(H_ / 64, (B_ * T_) / 64), 256>>>(
        ctx, query, W_out, b_out, out, B_ * T_, H_, 2 * H_);
}